// round 1
// baseline (speedup 1.0000x reference)
#include <cuda_runtime.h>

#define DIM   128
#define NTOK  49
#define NROW  56            // padded token rows (zero rows 49..55 -> guard-free GEMM)
#define NH    4
#define HD    32
#define NW    64
#define NBLK  4096
#define QST   392           // qkv smem row stride (384 + 8 pad)
#define WTILE 64
#define SCALE 0.17677669529663687f   // 1/sqrt(32)

// SMEM layout (floats):
//   xs   [56*128]      = 7168    (x tile; reused as attention output)
//   qk   [56*392]      = 21952   (qkv: cols 0..127 q, 128..255 k, 256..383 v)
//   scr  [4*49*49]     = 9604    (weight tile 128x64 = 8192 during GEMMs; attn scores otherwise)
//   ri   [49*49] int   = 2401
//   msk  [49*49]       = 2401
//   btb  [169*4]       = 676
//   bqs  [384], bps [128]
#define SMEM_FLOATS (7168 + 21952 + 9604 + 2401 + 2401 + 676 + 384 + 128)

extern __shared__ float smem[];

// 128xWTILE weight tile GEMM: out[m, nt0 + 0..63] = xs[m, 0..127] @ W[:, nt0..] + bias
__device__ __forceinline__ void gemm64(
    const float* __restrict__ W, int ldw, int nt0,
    const float* __restrict__ bias,
    const float* __restrict__ xs, float* __restrict__ wt,
    float* __restrict__ outp, int ost, int store_rows, int tid)
{
    // stage weight tile (coalesced global reads)
    for (int i = tid; i < 128 * WTILE; i += 256)
        wt[i] = W[(i >> 6) * ldw + nt0 + (i & 63)];
    __syncthreads();

    const int tx = tid & 31;      // 2 output cols: nt0 + tx*2
    const int ty = tid >> 5;      // 7 output rows: ty + 8r
    float acc0[7], acc1[7];
#pragma unroll
    for (int r = 0; r < 7; r++) { acc0[r] = 0.f; acc1[r] = 0.f; }

#pragma unroll 2
    for (int k4 = 0; k4 < 32; k4++) {
        float4 xv[7];
#pragma unroll
        for (int r = 0; r < 7; r++)
            xv[r] = *(const float4*)&xs[(ty + 8 * r) * DIM + k4 * 4];
        float2 wv[4];
#pragma unroll
        for (int kk = 0; kk < 4; kk++)
            wv[kk] = *(const float2*)&wt[(k4 * 4 + kk) * WTILE + tx * 2];
#pragma unroll
        for (int kk = 0; kk < 4; kk++) {
            const float wx = wv[kk].x, wy = wv[kk].y;
#pragma unroll
            for (int r = 0; r < 7; r++) {
                const float xvv = ((const float*)&xv[r])[kk];
                acc0[r] += xvv * wx;
                acc1[r] += xvv * wy;
            }
        }
    }

    const float b0 = bias[nt0 + tx * 2];
    const float b1 = bias[nt0 + tx * 2 + 1];
#pragma unroll
    for (int r = 0; r < 7; r++) {
        const int m = ty + 8 * r;
        if (m < store_rows) {
            float2 v = make_float2(acc0[r] + b0, acc1[r] + b1);
            *(float2*)&outp[m * ost + nt0 + tx * 2] = v;
        }
    }
    __syncthreads();   // wt reused by next tile
}

__global__ void __launch_bounds__(256, 1)
winattn_kernel(const float* __restrict__ x,
               const float* __restrict__ mask,
               const float* __restrict__ w_qkv,
               const float* __restrict__ b_qkv,
               const float* __restrict__ btab,
               const float* __restrict__ w_proj,
               const float* __restrict__ b_proj,
               const int*   __restrict__ rel_idx,
               float* __restrict__ out)
{
    const int b   = blockIdx.x;
    const int tid = threadIdx.x;

    float* xs  = smem;
    float* qk  = xs + NROW * DIM;
    float* scr = qk + NROW * QST;                 // 9604 floats
    int*   ri  = (int*)  (scr + NTOK * NTOK * NH);
    float* msk = (float*)(ri + NTOK * NTOK);
    float* btb = msk + NTOK * NTOK;
    float* bqs = btb + 169 * NH;
    float* bps = bqs + 3 * DIM;

    // ---- Stage A: load x tile + per-window constants ----
    const float* xg = x + (size_t)b * (NTOK * DIM);
    for (int i = tid; i < NTOK * DIM; i += 256) xs[i] = xg[i];
    for (int i = NTOK * DIM + tid; i < NROW * DIM; i += 256) xs[i] = 0.f;

    const int w = b & (NW - 1);
    const float* mg = mask + (size_t)w * (NTOK * NTOK);
    for (int i = tid; i < NTOK * NTOK; i += 256) { msk[i] = mg[i]; ri[i] = rel_idx[i]; }
    for (int i = tid; i < 169 * NH; i += 256) btb[i] = btab[i];
    if (tid < 3 * DIM) bqs[tid] = b_qkv[tid];
    if (tid < DIM)     bps[tid] = b_proj[tid];
    __syncthreads();

    // ---- Stage B: QKV = x @ w_qkv + b_qkv  (6 subtiles of 64 cols) ----
#pragma unroll 1
    for (int t = 0; t < 6; t++)
        gemm64(w_qkv, 3 * DIM, t * WTILE, bqs, xs, scr, qk, QST, NROW, tid);

    // ---- Stage C: per-head S = scale*q@k^T + bias + mask, row softmax ----
    const int hg = tid >> 6;       // head 0..3
    const int t  = tid & 63;
    {
        float* S = scr + hg * (NTOK * NTOK);
        if (t < NTOK) {
            const int n = t;
            const float* qrow = qk + n * QST + hg * HD;
            float4 qr[8];
#pragma unroll
            for (int i = 0; i < 8; i++) {
                float4 v = *(const float4*)&qrow[4 * i];
                v.x *= SCALE; v.y *= SCALE; v.z *= SCALE; v.w *= SCALE;
                qr[i] = v;
            }
            float* Srow = S + n * NTOK;
            const int*   rrow = ri  + n * NTOK;
            const float* mrow = msk + n * NTOK;
#pragma unroll 1
            for (int m = 0; m < NTOK; m++) {
                const float* krow = qk + m * QST + DIM + hg * HD;
                float s = 0.f;
#pragma unroll
                for (int i = 0; i < 8; i++) {
                    const float4 kv = *(const float4*)&krow[4 * i];
                    s += qr[i].x * kv.x + qr[i].y * kv.y
                       + qr[i].z * kv.z + qr[i].w * kv.w;
                }
                s += btb[rrow[m] * NH + hg] + mrow[m];
                Srow[m] = s;
            }
            float mx = -1e30f;
#pragma unroll 1
            for (int m = 0; m < NTOK; m++) mx = fmaxf(mx, Srow[m]);
            float sum = 0.f;
#pragma unroll 1
            for (int m = 0; m < NTOK; m++) {
                const float e = __expf(Srow[m] - mx);
                Srow[m] = e; sum += e;
            }
            const float inv = 1.f / sum;
#pragma unroll 1
            for (int m = 0; m < NTOK; m++) Srow[m] *= inv;
        }
    }
    __syncthreads();

    // ---- Stage D: ao = P @ v  (write into xs; rows 49..55 stay zero) ----
    {
        const int tx2 = t & 31;    // head-dim column
        const int tyh = t >> 5;    // row parity
        const float* Sh = scr + hg * (NTOK * NTOK);
        float acc[25];
#pragma unroll
        for (int r = 0; r < 25; r++) acc[r] = 0.f;
#pragma unroll 1
        for (int m = 0; m < NTOK; m++) {
            const float vv = qk[m * QST + 2 * DIM + hg * HD + tx2];
#pragma unroll
            for (int r = 0; r < 25; r++) {
                const int n = tyh + 2 * r;
                if (n < NTOK) acc[r] += Sh[n * NTOK + m] * vv;
            }
        }
#pragma unroll
        for (int r = 0; r < 25; r++) {
            const int n = tyh + 2 * r;
            if (n < NTOK) xs[n * DIM + hg * HD + tx2] = acc[r];
        }
    }
    __syncthreads();   // all S reads done before proj overwrites scr

    // ---- Stage E: out = ao @ w_proj + b_proj (direct coalesced global stores) ----
    float* og = out + (size_t)b * (NTOK * DIM);
    gemm64(w_proj, DIM, 0,      bps, xs, scr, og, DIM, NTOK, tid);
    gemm64(w_proj, DIM, WTILE,  bps, xs, scr, og, DIM, NTOK, tid);
}

extern "C" void kernel_launch(void* const* d_in, const int* in_sizes, int n_in,
                              void* d_out, int out_size)
{
    const float* x      = (const float*)d_in[0];
    const float* mask   = (const float*)d_in[1];
    const float* w_qkv  = (const float*)d_in[2];
    const float* b_qkv  = (const float*)d_in[3];
    const float* btab   = (const float*)d_in[4];
    const float* w_proj = (const float*)d_in[5];
    const float* b_proj = (const float*)d_in[6];
    const int*   relidx = (const int*)  d_in[7];
    float* out = (float*)d_out;

    const int smem_bytes = SMEM_FLOATS * (int)sizeof(float);
    cudaFuncSetAttribute(winattn_kernel,
                         cudaFuncAttributeMaxDynamicSharedMemorySize, smem_bytes);
    winattn_kernel<<<NBLK, 256, smem_bytes>>>(x, mask, w_qkv, b_qkv, btab,
                                              w_proj, b_proj, relidx, out);
}

// round 2
// speedup vs baseline: 1.6474x; 1.6474x over previous
#include <cuda_runtime.h>
#include <cstdint>

#define DIM   128
#define NTOK  49
#define MPAD  64
#define NH    4
#define HD    32
#define NW    64
#define NBLK  4096
#define XLD   132      // xs row stride (132 % 32 == 4 -> conflict-free frags)
#define QLD   388      // qkv row stride (388 % 32 == 4)
#define SLD   60       // score row stride (60 % 32 == 28)
#define WLD   72       // weight tile row stride (72 % 32 == 8)
#define SCALE 0.17677669529663687f

// SMEM layout (float offsets)
#define SM_X    0
#define SM_QK   (MPAD * XLD)                   // 8448
#define SM_SCR  (SM_QK + MPAD * QLD)           // 33280  (weight tile 128x72=9216 OR scores 4x64x60=15360)
#define SM_RI   (SM_SCR + NH * MPAD * SLD)     // 48640
#define SM_MSK  (SM_RI + NTOK * NTOK)          // 51041
#define SM_BTB  (SM_MSK + NTOK * NTOK)         // 53442
#define SM_BQ   (SM_BTB + 169 * NH)            // 54118
#define SM_BP   (SM_BQ + 3 * DIM)              // 54502
#define SMEM_FLOATS (SM_BP + DIM)              // 54630 floats = 218520 B (~213 KB)

extern __shared__ float smem[];

__device__ __forceinline__ uint32_t f2tf(float f) {
    uint32_t u;
    asm("cvt.rna.tf32.f32 %0, %1;" : "=r"(u) : "f"(f));
    return u;
}

// D = A(16x8, row) * B(8x8, col) + D, tf32 in, fp32 out
__device__ __forceinline__ void mma8(float* c, const uint32_t* a, uint32_t b0, uint32_t b1) {
    asm("mma.sync.aligned.m16n8k8.row.col.f32.tf32.tf32.f32 "
        "{%0,%1,%2,%3},{%4,%5,%6,%7},{%8,%9},{%0,%1,%2,%3};"
        : "+f"(c[0]), "+f"(c[1]), "+f"(c[2]), "+f"(c[3])
        : "r"(a[0]), "r"(a[1]), "r"(a[2]), "r"(a[3]), "r"(b0), "r"(b1));
}

__global__ void __launch_bounds__(256, 1)
winattn_kernel(const float* __restrict__ x,
               const float* __restrict__ mask,
               const float* __restrict__ w_qkv,
               const float* __restrict__ b_qkv,
               const float* __restrict__ btab,
               const float* __restrict__ w_proj,
               const float* __restrict__ b_proj,
               const int*   __restrict__ rel_idx,
               float* __restrict__ out)
{
    const int b    = blockIdx.x;
    const int tid  = threadIdx.x;
    const int wid  = tid >> 5;
    const int lane = tid & 31;
    const int gid  = lane >> 2;   // group-of-4 id (row within frag)
    const int tig  = lane & 3;    // thread-in-group (col within frag)

    float* xs  = smem + SM_X;
    float* qk  = smem + SM_QK;
    float* scr = smem + SM_SCR;
    int*   ri  = (int*)(smem + SM_RI);
    float* msk = smem + SM_MSK;
    float* btb = smem + SM_BTB;
    float* bqs = smem + SM_BQ;
    float* bps = smem + SM_BP;

    // ---- Stage A: load x (49x128 -> 64x132 padded with zero rows) + constants ----
    const float* xg = x + (size_t)b * (NTOK * DIM);
    for (int i = tid; i < NTOK * DIM; i += 256) xs[(i >> 7) * XLD + (i & 127)] = xg[i];
    for (int i = NTOK * XLD + tid; i < MPAD * XLD; i += 256) xs[i] = 0.f;

    const int w = b & (NW - 1);
    const float* mg = mask + (size_t)w * (NTOK * NTOK);
    for (int i = tid; i < NTOK * NTOK; i += 256) { msk[i] = mg[i]; ri[i] = rel_idx[i]; }
    for (int i = tid; i < 169 * NH; i += 256) btb[i] = btab[i];
    if (tid < 3 * DIM) bqs[tid] = b_qkv[tid];
    if (tid < DIM)     bps[tid] = b_proj[tid];
    __syncthreads();

    // ---- Stage B: QKV = x @ w_qkv + b  (M=64, N=384 in 6 tiles of 64, K=128) ----
    {
        uint32_t ax[16][4];
        const int m0 = (wid & 3) * 16;
#pragma unroll
        for (int kt = 0; kt < 16; kt++) {
            const float* p = xs + (m0 + gid) * XLD + kt * 8 + tig;
            ax[kt][0] = f2tf(p[0]);        ax[kt][1] = f2tf(p[8 * XLD]);
            ax[kt][2] = f2tf(p[4]);        ax[kt][3] = f2tf(p[8 * XLD + 4]);
        }
        const int nb = (wid >> 2) * 32;
#pragma unroll 1
        for (int t = 0; t < 6; t++) {
            __syncthreads();
            for (int i = tid; i < 128 * 64; i += 256)
                scr[(i >> 6) * WLD + (i & 63)] = w_qkv[(i >> 6) * 384 + t * 64 + (i & 63)];
            __syncthreads();
#pragma unroll
            for (int np = 0; np < 2; np++) {
                const int n0 = nb + np * 16;
                float c0[4] = {0,0,0,0}, c1[4] = {0,0,0,0};
#pragma unroll
                for (int kt = 0; kt < 16; kt++) {
                    const float* wp = scr + (kt * 8 + tig) * WLD;
                    uint32_t b00 = f2tf(wp[n0 + gid]),     b01 = f2tf(wp[4 * WLD + n0 + gid]);
                    uint32_t b10 = f2tf(wp[n0 + 8 + gid]), b11 = f2tf(wp[4 * WLD + n0 + 8 + gid]);
                    mma8(c0, ax[kt], b00, b01);
                    mma8(c1, ax[kt], b10, b11);
                }
                const int col = t * 64 + n0 + 2 * tig;
                const int r0 = m0 + gid, r1 = r0 + 8;
                float v0 = bqs[col], v1 = bqs[col + 1];
                *(float2*)&qk[r0 * QLD + col] = make_float2(c0[0] + v0, c0[1] + v1);
                *(float2*)&qk[r1 * QLD + col] = make_float2(c0[2] + v0, c0[3] + v1);
                float v2 = bqs[col + 8], v3 = bqs[col + 9];
                *(float2*)&qk[r0 * QLD + col + 8] = make_float2(c1[0] + v2, c1[1] + v3);
                *(float2*)&qk[r1 * QLD + col + 8] = make_float2(c1[2] + v2, c1[3] + v3);
            }
        }
    }
    __syncthreads();

    // ---- Stage C: S = scale*q @ k^T + relbias + mask  (per head: M=64, N=56, K=32) ----
    {
        const int h = wid >> 1, mh = wid & 1;   // 2 warps per head
        float* S = scr + h * (MPAD * SLD);
#pragma unroll
        for (int mi = 0; mi < 2; mi++) {
            const int m0 = (mh + 2 * mi) * 16;
            uint32_t aq[4][4];
#pragma unroll
            for (int kt = 0; kt < 4; kt++) {
                const float* p = qk + (m0 + gid) * QLD + h * HD + kt * 8 + tig;
                aq[kt][0] = f2tf(p[0] * SCALE);  aq[kt][1] = f2tf(p[8 * QLD] * SCALE);
                aq[kt][2] = f2tf(p[4] * SCALE);  aq[kt][3] = f2tf(p[8 * QLD + 4] * SCALE);
            }
#pragma unroll
            for (int nt = 0; nt < 7; nt++) {
                float c[4] = {0,0,0,0};
#pragma unroll
                for (int kt = 0; kt < 4; kt++) {
                    const float* kp = qk + (nt * 8 + gid) * QLD + DIM + h * HD + kt * 8 + tig;
                    mma8(c, aq[kt], f2tf(kp[0]), f2tf(kp[4]));
                }
#pragma unroll
                for (int e = 0; e < 4; e++) {
                    const int r  = m0 + gid + (e >> 1) * 8;
                    const int cc = nt * 8 + 2 * tig + (e & 1);
                    float v = c[e];
                    if (r < NTOK && cc < NTOK)
                        v += btb[ri[r * NTOK + cc] * NH + h] + msk[r * NTOK + cc];
                    S[r * SLD + cc] = v;
                }
            }
        }
    }
    __syncthreads();

    // ---- Softmax: one thread per (head,row); zero pad cols 49..55 for PV ----
    {
        const int hh = tid >> 6, rr = tid & 63;
        if (rr < NTOK) {
            float* Srow = scr + hh * (MPAD * SLD) + rr * SLD;
            float mx = -1e30f;
#pragma unroll 1
            for (int m = 0; m < NTOK; m++) mx = fmaxf(mx, Srow[m]);
            float sum = 0.f;
#pragma unroll 1
            for (int m = 0; m < NTOK; m++) { float e = __expf(Srow[m] - mx); Srow[m] = e; sum += e; }
            const float inv = 1.f / sum;
#pragma unroll 1
            for (int m = 0; m < NTOK; m++) Srow[m] *= inv;
#pragma unroll
            for (int m = NTOK; m < 56; m++) Srow[m] = 0.f;
        }
    }
    __syncthreads();

    // ---- Stage D: ao = P @ v  (per head: M=64, N=32, K=56) -> xs ----
    {
        const int h = wid >> 1, mh = wid & 1;
        const float* S = scr + h * (MPAD * SLD);
#pragma unroll
        for (int mi = 0; mi < 2; mi++) {
            const int m0 = (mh + 2 * mi) * 16;
            uint32_t ap[7][4];
#pragma unroll
            for (int kt = 0; kt < 7; kt++) {
                const float* p = S + (m0 + gid) * SLD + kt * 8 + tig;
                ap[kt][0] = f2tf(p[0]);  ap[kt][1] = f2tf(p[8 * SLD]);
                ap[kt][2] = f2tf(p[4]);  ap[kt][3] = f2tf(p[8 * SLD + 4]);
            }
            float c0[4] = {0,0,0,0}, c1[4] = {0,0,0,0};
#pragma unroll
            for (int kt = 0; kt < 7; kt++) {
                const float* vp = qk + (kt * 8 + tig) * QLD + 2 * DIM + h * HD + gid;
                uint32_t b00 = f2tf(vp[0]),  b01 = f2tf(vp[4 * QLD]);
                uint32_t b10 = f2tf(vp[8]),  b11 = f2tf(vp[4 * QLD + 8]);
                mma8(c0, ap[kt], b00, b01);
                mma8(c1, ap[kt], b10, b11);
            }
            float c2[4] = {0,0,0,0}, c3[4] = {0,0,0,0};
#pragma unroll
            for (int kt = 0; kt < 7; kt++) {
                const float* vp = qk + (kt * 8 + tig) * QLD + 2 * DIM + h * HD + 16 + gid;
                uint32_t b00 = f2tf(vp[0]),  b01 = f2tf(vp[4 * QLD]);
                uint32_t b10 = f2tf(vp[8]),  b11 = f2tf(vp[4 * QLD + 8]);
                mma8(c2, ap[kt], b00, b01);
                mma8(c3, ap[kt], b10, b11);
            }
            const int r0 = m0 + gid, r1 = r0 + 8;
            const int col = h * HD + 2 * tig;
            *(float2*)&xs[r0 * XLD + col]      = make_float2(c0[0], c0[1]);
            *(float2*)&xs[r1 * XLD + col]      = make_float2(c0[2], c0[3]);
            *(float2*)&xs[r0 * XLD + col + 8]  = make_float2(c1[0], c1[1]);
            *(float2*)&xs[r1 * XLD + col + 8]  = make_float2(c1[2], c1[3]);
            *(float2*)&xs[r0 * XLD + col + 16] = make_float2(c2[0], c2[1]);
            *(float2*)&xs[r1 * XLD + col + 16] = make_float2(c2[2], c2[3]);
            *(float2*)&xs[r0 * XLD + col + 24] = make_float2(c3[0], c3[1]);
            *(float2*)&xs[r1 * XLD + col + 24] = make_float2(c3[2], c3[3]);
        }
    }
    __syncthreads();

    // ---- Stage E: out = ao @ w_proj + b  (M=64, N=128 in 2 tiles, K=128) ----
    {
        uint32_t ao[16][4];
        const int m0 = (wid & 3) * 16;
#pragma unroll
        for (int kt = 0; kt < 16; kt++) {
            const float* p = xs + (m0 + gid) * XLD + kt * 8 + tig;
            ao[kt][0] = f2tf(p[0]);  ao[kt][1] = f2tf(p[8 * XLD]);
            ao[kt][2] = f2tf(p[4]);  ao[kt][3] = f2tf(p[8 * XLD + 4]);
        }
        const int nb = (wid >> 2) * 32;
        float* og = out + (size_t)b * (NTOK * DIM);
#pragma unroll 1
        for (int t = 0; t < 2; t++) {
            __syncthreads();
            for (int i = tid; i < 128 * 64; i += 256)
                scr[(i >> 6) * WLD + (i & 63)] = w_proj[(i >> 6) * DIM + t * 64 + (i & 63)];
            __syncthreads();
#pragma unroll
            for (int np = 0; np < 2; np++) {
                const int n0 = nb + np * 16;
                float c0[4] = {0,0,0,0}, c1[4] = {0,0,0,0};
#pragma unroll
                for (int kt = 0; kt < 16; kt++) {
                    const float* wp = scr + (kt * 8 + tig) * WLD;
                    mma8(c0, ao[kt], f2tf(wp[n0 + gid]),     f2tf(wp[4 * WLD + n0 + gid]));
                    mma8(c1, ao[kt], f2tf(wp[n0 + 8 + gid]), f2tf(wp[4 * WLD + n0 + 8 + gid]));
                }
                const int col = t * 64 + n0 + 2 * tig;
                const int r0 = m0 + gid, r1 = r0 + 8;
                const float v0 = bps[col], v1 = bps[col + 1];
                if (r0 < NTOK) *(float2*)&og[r0 * DIM + col] = make_float2(c0[0] + v0, c0[1] + v1);
                if (r1 < NTOK) *(float2*)&og[r1 * DIM + col] = make_float2(c0[2] + v0, c0[3] + v1);
                const float v2 = bps[col + 8], v3 = bps[col + 9];
                if (r0 < NTOK) *(float2*)&og[r0 * DIM + col + 8] = make_float2(c1[0] + v2, c1[1] + v3);
                if (r1 < NTOK) *(float2*)&og[r1 * DIM + col + 8] = make_float2(c1[2] + v2, c1[3] + v3);
            }
        }
    }
}

extern "C" void kernel_launch(void* const* d_in, const int* in_sizes, int n_in,
                              void* d_out, int out_size)
{
    const float* x      = (const float*)d_in[0];
    const float* mask   = (const float*)d_in[1];
    const float* w_qkv  = (const float*)d_in[2];
    const float* b_qkv  = (const float*)d_in[3];
    const float* btab   = (const float*)d_in[4];
    const float* w_proj = (const float*)d_in[5];
    const float* b_proj = (const float*)d_in[6];
    const int*   relidx = (const int*)  d_in[7];
    float* out = (float*)d_out;

    const int smem_bytes = SMEM_FLOATS * (int)sizeof(float);
    cudaFuncSetAttribute(winattn_kernel,
                         cudaFuncAttributeMaxDynamicSharedMemorySize, smem_bytes);
    winattn_kernel<<<NBLK, 256, smem_bytes>>>(x, mask, w_qkv, b_qkv, btab,
                                              w_proj, b_proj, relidx, out);
}